// round 9
// baseline (speedup 1.0000x reference)
#include <cuda_runtime.h>
#include <cuda_fp16.h>
#include <math.h>
#include <cstdint>

#define B_   32
#define T_   2000
#define H_   256
#define S_   63
#define TM1  1999            // T-1
#define M1   63968           // B*(T-1)
#define M1P  64000           // padded row count
#define K1   512             // 2*H
#define N1   256             // H

// Scratch (device globals: allocation-guard safe)
__device__ __align__(16) uint4    g_hfrag[4000 * 16 * 32]; // h fp16, gemm2 A-frag packed
__device__ __align__(16) float    g_trans[M1P * S_];       // boundary trans rows only
__device__ __align__(16) uint4    g_w1pack[16384];         // W1^T fp16 A-frags
__device__ __align__(16) uint2    g_w2pack[4096];          // W2 fp16 B-frags

__device__ __forceinline__ uint32_t h2u(__half2 h) {
    return *reinterpret_cast<uint32_t*>(&h);
}

__device__ __forceinline__ void mma_f16(float* c, uint32_t a0, uint32_t a1,
                                        uint32_t a2, uint32_t a3,
                                        uint32_t b0, uint32_t b1) {
    asm volatile(
        "mma.sync.aligned.m16n8k16.row.col.f32.f16.f16.f32 "
        "{%0,%1,%2,%3}, {%4,%5,%6,%7}, {%8,%9}, {%0,%1,%2,%3};"
        : "+f"(c[0]), "+f"(c[1]), "+f"(c[2]), "+f"(c[3])
        : "r"(a0), "r"(a1), "r"(a2), "r"(a3), "r"(b0), "r"(b1));
}

__device__ __forceinline__ void ldsm4(uint32_t& r0, uint32_t& r1,
                                      uint32_t& r2, uint32_t& r3, uint32_t addr) {
    asm volatile("ldmatrix.sync.aligned.m8n8.x4.shared.b16 {%0,%1,%2,%3}, [%4];"
                 : "=r"(r0), "=r"(r1), "=r"(r2), "=r"(r3) : "r"(addr));
}

__device__ __forceinline__ uint32_t smem_u32(const void* p) {
    uint32_t a;
    asm("{ .reg .u64 t; cvta.to.shared.u64 t, %1; cvt.u32.u64 %0, t; }"
        : "=r"(a) : "l"(p));
    return a;
}

// ===========================================================================
// Prep (merged): blocks 0..63 pack W1, blocks 64..67 pack W2.
// ===========================================================================
__global__ __launch_bounds__(256) void prep_weights(
    const float* __restrict__ W1, const float* __restrict__ W2)
{
    if (blockIdx.x < 64) {
        int idx   = blockIdx.x * 256 + threadIdx.x;   // 0..16383
        int lane  = idx & 31;
        int s     = (idx >> 5) & 1;
        int kstep = (idx >> 6) & 31;
        int q     = (idx >> 11) & 7;

        int n0 = q * 32 + s * 16 + (lane >> 2);
        int k0 = kstep * 16 + (lane & 3) * 2;

        uint4 o;
        o.x = h2u(__floats2half2_rn(W1[(long)k0 * N1 + n0],       W1[(long)(k0 + 1) * N1 + n0]));
        o.y = h2u(__floats2half2_rn(W1[(long)k0 * N1 + n0 + 8],   W1[(long)(k0 + 1) * N1 + n0 + 8]));
        o.z = h2u(__floats2half2_rn(W1[(long)(k0 + 8) * N1 + n0],     W1[(long)(k0 + 9) * N1 + n0]));
        o.w = h2u(__floats2half2_rn(W1[(long)(k0 + 8) * N1 + n0 + 8], W1[(long)(k0 + 9) * N1 + n0 + 8]));
        g_w1pack[idx] = o;
    } else {
        int idx  = (blockIdx.x - 64) * 256 + threadIdx.x;   // 0..1023 per block set
        if (idx >= 4096) return;
        int lane = idx & 31;
        int nb   = (idx >> 5) & 7;
        int kt   = idx >> 8;
        int k = kt * 16 + (lane & 3) * 2;
        int n = nb * 8 + (lane >> 2);
        float w00 = (n < S_) ? W2[(long)k * S_ + n]       : 0.f;
        float w01 = (n < S_) ? W2[(long)(k + 1) * S_ + n] : 0.f;
        float w10 = (n < S_) ? W2[(long)(k + 8) * S_ + n] : 0.f;
        float w11 = (n < S_) ? W2[(long)(k + 9) * S_ + n] : 0.f;
        uint2 o;
        o.x = h2u(__floats2half2_rn(w00, w01));
        o.y = h2u(__floats2half2_rn(w10, w11));
        g_w2pack[idx] = o;
    }
}

// ===========================================================================
// GEMM1 (fp16 mma.sync + ldmatrix): h = relu(pairs @ W1 + b1)  [unchanged R8]
// ===========================================================================
#define BSTW 20   // uint32 words per B row (40 halfs = 80 bytes)
__global__ __launch_bounds__(256, 2) void gemm1_tc(
    const float* __restrict__ emb, const float* __restrict__ b1)
{
    extern __shared__ __align__(16) char dynsm[];
    uint32_t* sB0 = reinterpret_cast<uint32_t*>(dynsm);   // [2][64*20] mainloop
    __half*   sT  = reinterpret_cast<__half*>(dynsm);     // [64][264] epilogue
    const uint32_t sbAddr = smem_u32(dynsm);

    const int tid  = threadIdx.x;
    const int warp = tid >> 5;     // hidden 32-block (0..7)
    const int lane = tid & 31;
    const int g    = lane >> 2;
    const int t    = lane & 3;
    const int mBase = blockIdx.x * 64;

    const int lmJ     = (lane >> 4);
    const int lmPiece = (lane >> 3) & 1;
    const int lmRow   = lane & 7;

    const int r  = tid >> 2;             // 0..63
    const int ch = (tid & 3) * 8;
    int m = mBase + r;
    if (m >= M1) m = M1 - 1;
    const int b = m / TM1;
    const int tt = m - b * TM1;
    const float* rowT  = emb + ((long)b * T_ + tt) * H_;
    const float* rowT1 = rowT + H_;

    float acc[2][8][4];
    #pragma unroll
    for (int s = 0; s < 2; s++)
        #pragma unroll
        for (int j = 0; j < 8; j++)
            #pragma unroll
            for (int d = 0; d < 4; d++) acc[s][j][d] = 0.f;

    {
        float4 v0 = *reinterpret_cast<const float4*>(rowT1 + ch);
        float4 v1 = *reinterpret_cast<const float4*>(rowT1 + ch + 4);
        uint4 o;
        o.x = h2u(__floats2half2_rn(v0.x, v0.y));
        o.y = h2u(__floats2half2_rn(v0.z, v0.w));
        o.z = h2u(__floats2half2_rn(v1.x, v1.y));
        o.w = h2u(__floats2half2_rn(v1.z, v1.w));
        *reinterpret_cast<uint4*>(&sB0[r * BSTW + ch / 2]) = o;
    }
    __syncthreads();

    for (int kt = 0; kt < 16; kt++) {
        const int cur = kt & 1;
        const uint32_t sCaddr = sbAddr + cur * (64 * BSTW * 4);

        float4 vn0, vn1;
        if (kt < 15) {
            const int kg = (kt + 1) * 32;
            const float* src = (kg < H_) ? (rowT1 + kg) : (rowT + (kg - H_));
            vn0 = *reinterpret_cast<const float4*>(src + ch);
            vn1 = *reinterpret_cast<const float4*>(src + ch + 4);
        }

        #pragma unroll
        for (int ks = 0; ks < 2; ks++) {
            long aIdx = (((long)(warp * 32 + kt * 2 + ks)) * 2) * 32 + lane;
            uint4 A0 = g_w1pack[aIdx];
            uint4 A1 = g_w1pack[aIdx + 32];

            #pragma unroll
            for (int jp = 0; jp < 4; jp++) {
                int jm = jp * 2 + lmJ;
                uint32_t addr = sCaddr + (jm * 8 + lmRow) * 80
                              + ks * 32 + lmPiece * 16;
                uint32_t r0, r1, r2, r3;
                ldsm4(r0, r1, r2, r3, addr);
                mma_f16(acc[0][jp * 2],     A0.x, A0.y, A0.z, A0.w, r0, r1);
                mma_f16(acc[1][jp * 2],     A1.x, A1.y, A1.z, A1.w, r0, r1);
                mma_f16(acc[0][jp * 2 + 1], A0.x, A0.y, A0.z, A0.w, r2, r3);
                mma_f16(acc[1][jp * 2 + 1], A1.x, A1.y, A1.z, A1.w, r2, r3);
            }
        }

        if (kt < 15) {
            uint32_t* sN = sB0 + (cur ^ 1) * (64 * BSTW);
            uint4 o;
            o.x = h2u(__floats2half2_rn(vn0.x, vn0.y));
            o.y = h2u(__floats2half2_rn(vn0.z, vn0.w));
            o.z = h2u(__floats2half2_rn(vn1.x, vn1.y));
            o.w = h2u(__floats2half2_rn(vn1.z, vn1.w));
            *reinterpret_cast<uint4*>(&sN[r * BSTW + ch / 2]) = o;
        }
        __syncthreads();
    }

    #pragma unroll
    for (int s = 0; s < 2; s++) {
        int n_g = warp * 32 + s * 16 + g;
        float bn0 = __ldg(&b1[n_g]);
        float bn8 = __ldg(&b1[n_g + 8]);
        #pragma unroll
        for (int j = 0; j < 8; j++) {
            int m_loc = j * 8 + t * 2;
            sT[m_loc * 264 + n_g]           = __float2half(fmaxf(acc[s][j][0] + bn0, 0.f));
            sT[(m_loc + 1) * 264 + n_g]     = __float2half(fmaxf(acc[s][j][1] + bn0, 0.f));
            sT[m_loc * 264 + n_g + 8]       = __float2half(fmaxf(acc[s][j][2] + bn8, 0.f));
            sT[(m_loc + 1) * 264 + n_g + 8] = __float2half(fmaxf(acc[s][j][3] + bn8, 0.f));
        }
    }
    __syncthreads();

    {
        const long mblkBase = (long)blockIdx.x * 4;
        #pragma unroll
        for (int ktl = 0; ktl < 2; ktl++) {
            const int kt = warp * 2 + ktl;
            const int col = kt * 16 + t * 2;
            #pragma unroll
            for (int mb = 0; mb < 4; mb++) {
                int row = mb * 16 + g;
                uint4 o;
                o.x = *reinterpret_cast<const uint32_t*>(&sT[row * 264 + col]);
                o.y = *reinterpret_cast<const uint32_t*>(&sT[(row + 8) * 264 + col]);
                o.z = *reinterpret_cast<const uint32_t*>(&sT[row * 264 + col + 8]);
                o.w = *reinterpret_cast<const uint32_t*>(&sT[(row + 8) * 264 + col + 8]);
                g_hfrag[((mblkBase + mb) * 16 + kt) * 32 + lane] = o;
            }
        }
    }
}

// ===========================================================================
// Fused GEMM2 + ALIGN: trans tile (in smem) -> softmax outputs directly.
//   MMA: warp 32m x 64n, CTA 256m, K=256.  Staging includes +b2.
//   Align: each warp emits outputs for its 32 owned rows (trans rows m-1,m
//   read from smem).  Boundary rows (i==0, t>=1) deferred to cleanup via
//   tiny g_trans writes (rows i==0 and i==255 only).
// ===========================================================================
__device__ __forceinline__ void softmax_emit(float v0, float v1, bool has1,
                                             float* ob, int lane) {
    float mx = fmaxf(v0, v1);
    #pragma unroll
    for (int o = 16; o > 0; o >>= 1) mx = fmaxf(mx, __shfl_xor_sync(0xffffffff, mx, o));
    float e0 = __expf(v0 - mx);
    float e1 = has1 ? __expf(v1 - mx) : 0.f;
    float sum = e0 + e1;
    #pragma unroll
    for (int o = 16; o > 0; o >>= 1) sum += __shfl_xor_sync(0xffffffff, sum, o);
    float inv = 1.f / sum;
    ob[lane] = e0 * inv;
    if (has1) ob[lane + 32] = e1 * inv;
}

__global__ __launch_bounds__(256, 2) void gemm2align(
    const float* __restrict__ logits, const int* __restrict__ kw,
    const float* __restrict__ b2, float* __restrict__ out)
{
    extern __shared__ __align__(16) float sm2[];   // [256][65]

    const int tid  = threadIdx.x;
    const int warp = tid >> 5;
    const int lane = tid & 31;
    const int g = lane >> 2;
    const int t = lane & 3;
    const long mblk0 = (long)blockIdx.x * 16 + warp * 2;

    float acc[2][8][4];
    #pragma unroll
    for (int mf = 0; mf < 2; mf++)
        #pragma unroll
        for (int nb = 0; nb < 8; nb++)
            #pragma unroll
            for (int d = 0; d < 4; d++) acc[mf][nb][d] = 0.f;

    uint4 Af0 = g_hfrag[(mblk0 * 16 + 0) * 32 + lane];
    uint4 Af1 = g_hfrag[((mblk0 + 1) * 16 + 0) * 32 + lane];

    #pragma unroll
    for (int kt = 0; kt < 16; kt++) {
        uint4 An0, An1;
        if (kt < 15) {
            An0 = g_hfrag[(mblk0 * 16 + kt + 1) * 32 + lane];
            An1 = g_hfrag[((mblk0 + 1) * 16 + kt + 1) * 32 + lane];
        }
        #pragma unroll
        for (int nb = 0; nb < 8; nb++) {
            uint2 bf = __ldg(&g_w2pack[((long)kt * 8 + nb) * 32 + lane]);
            mma_f16(acc[0][nb], Af0.x, Af0.y, Af0.z, Af0.w, bf.x, bf.y);
            mma_f16(acc[1][nb], Af1.x, Af1.y, Af1.z, Af1.w, bf.x, bf.y);
        }
        if (kt < 15) { Af0 = An0; Af1 = An1; }
    }

    // stage (bias added) to smem [m 256][n 64 (pad 65)]
    #pragma unroll
    for (int mf = 0; mf < 2; mf++) {
        int mr = warp * 32 + mf * 16 + g;
        #pragma unroll
        for (int nb = 0; nb < 8; nb++) {
            int n = nb * 8 + t * 2;
            float bn0 = __ldg(&b2[n]);
            float bn1 = (n + 1 < S_) ? __ldg(&b2[n + 1]) : 0.f;
            sm2[mr * 65 + n]           = acc[mf][nb][0] + bn0;
            sm2[mr * 65 + n + 1]       = acc[mf][nb][1] + bn1;
            sm2[(mr + 8) * 65 + n]     = acc[mf][nb][2] + bn0;
            sm2[(mr + 8) * 65 + n + 1] = acc[mf][nb][3] + bn1;
        }
    }
    __syncthreads();

    const long mB = (long)blockIdx.x * 256;

    // boundary trans rows for the cleanup kernel (rows 0 and 255 only)
    if (tid < S_ && mB < M1)
        g_trans[mB * S_ + tid] = sm2[tid];
    if (tid >= 128 && tid < 128 + S_ && mB + 255 < M1)
        g_trans[(mB + 255) * S_ + (tid - 128)] = sm2[255 * 65 + (tid - 128)];

    // align: warp handles rows warp*32 .. warp*32+31
    const bool has1 = (lane + 32 < S_);
    for (int j = 0; j < 32; j++) {
        const int i = warp * 32 + j;
        const long m = mB + i;
        if (m >= M1) break;
        const int b = (int)(m / TM1);
        const int tt = (int)(m - (long)b * TM1);
        const float* Lb = logits + (long)b * T_ * S_;

        float tri0 = sm2[i * 65 + lane];
        float tri1 = has1 ? sm2[i * 65 + lane + 32] : 0.f;

        if (tt == 0) {
            // output (b, 0): f0 + lp[1] + tr[0]
            float a0 = __ldg(&Lb[lane]);
            float a1 = has1 ? __ldg(&Lb[lane + 32]) : -INFINITY;
            float mx = fmaxf(a0, a1);
            #pragma unroll
            for (int o = 16; o > 0; o >>= 1) mx = fmaxf(mx, __shfl_xor_sync(0xffffffff, mx, o));
            float se = __expf(a0 - mx) + (has1 ? __expf(a1 - mx) : 0.f);
            #pragma unroll
            for (int o = 16; o > 0; o >>= 1) se += __shfl_xor_sync(0xffffffff, se, o);
            float lse = mx + __logf(se);
            int k0 = __ldg(&kw[b * 32]);
            float logp0 = __ldg(&Lb[k0]) - lse;
            float v0 = ((lane == 0) ? logp0 : 0.f) + __ldg(&Lb[S_ + lane]) + tri0;
            float v1 = has1 ? (__ldg(&Lb[S_ + lane + 32]) + tri1) : -INFINITY;
            softmax_emit(v0, v1, has1, out + (long)b * T_ * S_, lane);
        } else if (i > 0) {
            // output (b, tt): lp[tt] + lp[tt+1] + tr[tt-1] + tr[tt]
            float v0 = __ldg(&Lb[(long)tt * S_ + lane]) + __ldg(&Lb[(long)(tt + 1) * S_ + lane])
                     + sm2[(i - 1) * 65 + lane] + tri0;
            float v1 = has1
                ? (__ldg(&Lb[(long)tt * S_ + lane + 32]) + __ldg(&Lb[(long)(tt + 1) * S_ + lane + 32])
                   + sm2[(i - 1) * 65 + lane + 32] + tri1)
                : -INFINITY;
            softmax_emit(v0, v1, has1, out + ((long)b * T_ + tt) * S_, lane);
        }
        if (tt == TM1 - 1) {
            // output (b, T-1): lp[T-1] + tr[T-2]
            float v0 = __ldg(&Lb[(long)(T_ - 1) * S_ + lane]) + tri0;
            float v1 = has1 ? (__ldg(&Lb[(long)(T_ - 1) * S_ + lane + 32]) + tri1) : -INFINITY;
            softmax_emit(v0, v1, has1, out + ((long)b * T_ + T_ - 1) * S_, lane);
        }
    }
}

// ===========================================================================
// Cleanup: boundary outputs (m = 256c, t >= 1) using g_trans boundary rows.
// ===========================================================================
__global__ __launch_bounds__(256) void cleanup_kernel(
    const float* __restrict__ logits, float* __restrict__ out)
{
    const int task = blockIdx.x * 8 + (threadIdx.x >> 5);
    if (task >= 249) return;
    const long m = (long)(task + 1) * 256;
    const int b = (int)(m / TM1);
    const int t = (int)(m - (long)b * TM1);
    if (t == 0) return;

    const int lane = threadIdx.x & 31;
    const bool has1 = (lane + 32 < S_);
    const float* Lb = logits + (long)b * T_ * S_;

    float v0 = __ldg(&Lb[(long)t * S_ + lane]) + __ldg(&Lb[(long)(t + 1) * S_ + lane])
             + g_trans[(m - 1) * S_ + lane] + g_trans[m * S_ + lane];
    float v1 = has1
        ? (__ldg(&Lb[(long)t * S_ + lane + 32]) + __ldg(&Lb[(long)(t + 1) * S_ + lane + 32])
           + g_trans[(m - 1) * S_ + lane + 32] + g_trans[m * S_ + lane + 32])
        : -INFINITY;
    softmax_emit(v0, v1, has1, out + ((long)b * T_ + t) * S_, lane);
}

// ===========================================================================
extern "C" void kernel_launch(void* const* d_in, const int* in_sizes, int n_in,
                              void* d_out, int out_size) {
    const float* logits = (const float*)d_in[0];   // (B,T,S)
    const float* emb    = (const float*)d_in[1];   // (B,T,H)
    const int*   kw     = (const int*)  d_in[2];   // (B,32)
    const float* W1     = (const float*)d_in[3];   // (2H,H)
    const float* b1     = (const float*)d_in[4];   // (H,)
    const float* W2     = (const float*)d_in[5];   // (H,S)
    const float* b2     = (const float*)d_in[6];   // (S,)
    float*       out    = (float*)d_out;           // (B,T,S)

    const int smem1 = 64 * 264 * 2;        // 33792
    const int smem2 = 256 * 65 * 4;        // 66560
    cudaFuncSetAttribute(gemm1_tc, cudaFuncAttributeMaxDynamicSharedMemorySize, smem1);
    cudaFuncSetAttribute(gemm2align, cudaFuncAttributeMaxDynamicSharedMemorySize, smem2);

    prep_weights<<<80, 256>>>(W1, W2);
    gemm1_tc<<<1000, 256, smem1>>>(emb, b1);
    gemm2align<<<250, 256, smem2>>>(logits, kw, b2, out);
    cleanup_kernel<<<32, 256>>>(logits, out);
}

// round 10
// speedup vs baseline: 1.2741x; 1.2741x over previous
#include <cuda_runtime.h>
#include <cuda_fp16.h>
#include <math.h>
#include <cstdint>

#define B_   32
#define T_   2000
#define H_   256
#define S_   63
#define TRS  64              // g_trans row stride (padded for alignment)
#define TM1  1999            // T-1
#define M1   63968           // B*(T-1)
#define M1P  64000           // padded row count
#define K1   512             // 2*H
#define N1   256             // H

// Scratch (device globals: allocation-guard safe)
__device__ __align__(16) float    g_trans[M1P * TRS];     // transition scores (stride 64)
__device__ __align__(16) uint4    g_w1pack[16384];        // W1^T fp16 A-frags
__device__ __align__(16) uint2    g_w2pack[4096];         // W2 fp16 B-frags

__device__ __forceinline__ uint32_t h2u(__half2 h) {
    return *reinterpret_cast<uint32_t*>(&h);
}

__device__ __forceinline__ void mma_f16(float* c, uint32_t a0, uint32_t a1,
                                        uint32_t a2, uint32_t a3,
                                        uint32_t b0, uint32_t b1) {
    asm volatile(
        "mma.sync.aligned.m16n8k16.row.col.f32.f16.f16.f32 "
        "{%0,%1,%2,%3}, {%4,%5,%6,%7}, {%8,%9}, {%0,%1,%2,%3};"
        : "+f"(c[0]), "+f"(c[1]), "+f"(c[2]), "+f"(c[3])
        : "r"(a0), "r"(a1), "r"(a2), "r"(a3), "r"(b0), "r"(b1));
}

__device__ __forceinline__ void ldsm4(uint32_t& r0, uint32_t& r1,
                                      uint32_t& r2, uint32_t& r3, uint32_t addr) {
    asm volatile("ldmatrix.sync.aligned.m8n8.x4.shared.b16 {%0,%1,%2,%3}, [%4];"
                 : "=r"(r0), "=r"(r1), "=r"(r2), "=r"(r3) : "r"(addr));
}

__device__ __forceinline__ uint32_t smem_u32(const void* p) {
    uint32_t a;
    asm("{ .reg .u64 t; cvta.to.shared.u64 t, %1; cvt.u32.u64 %0, t; }"
        : "=r"(a) : "l"(p));
    return a;
}

// ===========================================================================
// Prep (merged): blocks 0..63 pack W1, blocks 64..79 pack W2.
// ===========================================================================
__global__ __launch_bounds__(256) void prep_weights(
    const float* __restrict__ W1, const float* __restrict__ W2)
{
    if (blockIdx.x < 64) {
        int idx   = blockIdx.x * 256 + threadIdx.x;   // 0..16383
        int lane  = idx & 31;
        int s     = (idx >> 5) & 1;
        int kstep = (idx >> 6) & 31;
        int q     = (idx >> 11) & 7;

        int n0 = q * 32 + s * 16 + (lane >> 2);
        int k0 = kstep * 16 + (lane & 3) * 2;

        uint4 o;
        o.x = h2u(__floats2half2_rn(W1[(long)k0 * N1 + n0],       W1[(long)(k0 + 1) * N1 + n0]));
        o.y = h2u(__floats2half2_rn(W1[(long)k0 * N1 + n0 + 8],   W1[(long)(k0 + 1) * N1 + n0 + 8]));
        o.z = h2u(__floats2half2_rn(W1[(long)(k0 + 8) * N1 + n0],     W1[(long)(k0 + 9) * N1 + n0]));
        o.w = h2u(__floats2half2_rn(W1[(long)(k0 + 8) * N1 + n0 + 8], W1[(long)(k0 + 9) * N1 + n0 + 8]));
        g_w1pack[idx] = o;
    } else {
        int idx  = (blockIdx.x - 64) * 256 + threadIdx.x;
        if (idx >= 4096) return;
        int lane = idx & 31;
        int nb   = (idx >> 5) & 7;
        int kt   = idx >> 8;
        int k = kt * 16 + (lane & 3) * 2;
        int n = nb * 8 + (lane >> 2);
        float w00 = (n < S_) ? W2[(long)k * S_ + n]       : 0.f;
        float w01 = (n < S_) ? W2[(long)(k + 1) * S_ + n] : 0.f;
        float w10 = (n < S_) ? W2[(long)(k + 8) * S_ + n] : 0.f;
        float w11 = (n < S_) ? W2[(long)(k + 9) * S_ + n] : 0.f;
        uint2 o;
        o.x = h2u(__floats2half2_rn(w00, w01));
        o.y = h2u(__floats2half2_rn(w10, w11));
        g_w2pack[idx] = o;
    }
}

// ===========================================================================
// Fused GEMM1+GEMM2 (fp16 mma.sync + ldmatrix):
//   h = relu(pairs @ W1 + b1)  (mainloop, CTA 256hid x 64m, 8 warps)
//   trans = h @ W2 + b2        (epilogue, A from smem h tile via ldmatrix,
//                               warps split N; writes g_trans stride 64)
// ===========================================================================
#define BSTW 20   // uint32 words per B row (40 halfs = 80 bytes)
__global__ __launch_bounds__(256, 2) void gemm1_fused(
    const float* __restrict__ emb, const float* __restrict__ b1,
    const float* __restrict__ b2)
{
    extern __shared__ __align__(16) char dynsm[];
    uint32_t* sB0 = reinterpret_cast<uint32_t*>(dynsm);   // [2][64*20] mainloop
    __half*   sT  = reinterpret_cast<__half*>(dynsm);     // [64][264] epilogue h tile
    const uint32_t sbAddr = smem_u32(dynsm);

    const int tid  = threadIdx.x;
    const int warp = tid >> 5;     // hidden 32-block (0..7)
    const int lane = tid & 31;
    const int g    = lane >> 2;
    const int t    = lane & 3;
    const int mBase = blockIdx.x * 64;

    const int lmJ     = (lane >> 4);
    const int lmPiece = (lane >> 3) & 1;
    const int lmRow   = lane & 7;

    const int r  = tid >> 2;             // 0..63
    const int ch = (tid & 3) * 8;
    int m = mBase + r;
    if (m >= M1) m = M1 - 1;
    const int b = m / TM1;
    const int tt = m - b * TM1;
    const float* rowT  = emb + ((long)b * T_ + tt) * H_;
    const float* rowT1 = rowT + H_;

    float acc[2][8][4];
    #pragma unroll
    for (int s = 0; s < 2; s++)
        #pragma unroll
        for (int j = 0; j < 8; j++)
            #pragma unroll
            for (int d = 0; d < 4; d++) acc[s][j][d] = 0.f;

    {
        float4 v0 = *reinterpret_cast<const float4*>(rowT1 + ch);
        float4 v1 = *reinterpret_cast<const float4*>(rowT1 + ch + 4);
        uint4 o;
        o.x = h2u(__floats2half2_rn(v0.x, v0.y));
        o.y = h2u(__floats2half2_rn(v0.z, v0.w));
        o.z = h2u(__floats2half2_rn(v1.x, v1.y));
        o.w = h2u(__floats2half2_rn(v1.z, v1.w));
        *reinterpret_cast<uint4*>(&sB0[r * BSTW + ch / 2]) = o;
    }
    __syncthreads();

    for (int kt = 0; kt < 16; kt++) {
        const int cur = kt & 1;
        const uint32_t sCaddr = sbAddr + cur * (64 * BSTW * 4);

        float4 vn0, vn1;
        if (kt < 15) {
            const int kg = (kt + 1) * 32;
            const float* src = (kg < H_) ? (rowT1 + kg) : (rowT + (kg - H_));
            vn0 = *reinterpret_cast<const float4*>(src + ch);
            vn1 = *reinterpret_cast<const float4*>(src + ch + 4);
        }

        #pragma unroll
        for (int ks = 0; ks < 2; ks++) {
            long aIdx = (((long)(warp * 32 + kt * 2 + ks)) * 2) * 32 + lane;
            uint4 A0 = g_w1pack[aIdx];
            uint4 A1 = g_w1pack[aIdx + 32];

            #pragma unroll
            for (int jp = 0; jp < 4; jp++) {
                int jm = jp * 2 + lmJ;
                uint32_t addr = sCaddr + (jm * 8 + lmRow) * 80
                              + ks * 32 + lmPiece * 16;
                uint32_t r0, r1, r2, r3;
                ldsm4(r0, r1, r2, r3, addr);
                mma_f16(acc[0][jp * 2],     A0.x, A0.y, A0.z, A0.w, r0, r1);
                mma_f16(acc[1][jp * 2],     A1.x, A1.y, A1.z, A1.w, r0, r1);
                mma_f16(acc[0][jp * 2 + 1], A0.x, A0.y, A0.z, A0.w, r2, r3);
                mma_f16(acc[1][jp * 2 + 1], A1.x, A1.y, A1.z, A1.w, r2, r3);
            }
        }

        if (kt < 15) {
            uint32_t* sN = sB0 + (cur ^ 1) * (64 * BSTW);
            uint4 o;
            o.x = h2u(__floats2half2_rn(vn0.x, vn0.y));
            o.y = h2u(__floats2half2_rn(vn0.z, vn0.w));
            o.z = h2u(__floats2half2_rn(vn1.x, vn1.y));
            o.w = h2u(__floats2half2_rn(vn1.z, vn1.w));
            *reinterpret_cast<uint4*>(&sN[r * BSTW + ch / 2]) = o;
        }
        __syncthreads();
    }

    // Epilogue pass 1: +b1, relu, fp16 -> smem h tile [m 64][hid 256 (stride 264)]
    #pragma unroll
    for (int s = 0; s < 2; s++) {
        int n_g = warp * 32 + s * 16 + g;
        float bn0 = __ldg(&b1[n_g]);
        float bn8 = __ldg(&b1[n_g + 8]);
        #pragma unroll
        for (int j = 0; j < 8; j++) {
            int m_loc = j * 8 + t * 2;
            sT[m_loc * 264 + n_g]           = __float2half(fmaxf(acc[s][j][0] + bn0, 0.f));
            sT[(m_loc + 1) * 264 + n_g]     = __float2half(fmaxf(acc[s][j][1] + bn0, 0.f));
            sT[m_loc * 264 + n_g + 8]       = __float2half(fmaxf(acc[s][j][2] + bn8, 0.f));
            sT[(m_loc + 1) * 264 + n_g + 8] = __float2half(fmaxf(acc[s][j][3] + bn8, 0.f));
        }
    }
    __syncthreads();

    // Epilogue pass 2 (fused gemm2): trans = h @ W2 + b2
    //   warp w: mb = w&3 (m16-block), nhalf = w>>2 (32 of 64 n-cols).
    //   A frags from sT via ldmatrix (rows mb*16+.., col kt*16; stride 528B
    //   -> successive rows 16B apart mod 128 -> conflict-free).
    {
        const int mb    = warp & 3;
        const int nhalf = warp >> 2;

        float acc2[4][4];
        #pragma unroll
        for (int nbl = 0; nbl < 4; nbl++)
            #pragma unroll
            for (int d = 0; d < 4; d++) acc2[nbl][d] = 0.f;

        #pragma unroll
        for (int kt = 0; kt < 16; kt++) {
            uint32_t addr = sbAddr + (mb * 16 + (lane & 15)) * 528
                          + kt * 32 + (lane >> 4) * 16;
            uint32_t a0, a1, a2, a3;
            ldsm4(a0, a1, a2, a3, addr);
            #pragma unroll
            for (int nbl = 0; nbl < 4; nbl++) {
                int nb = nhalf * 4 + nbl;
                uint2 bf = __ldg(&g_w2pack[((long)kt * 8 + nb) * 32 + lane]);
                mma_f16(acc2[nbl], a0, a1, a2, a3, bf.x, bf.y);
            }
        }

        const long mB = (long)blockIdx.x * 64;
        #pragma unroll
        for (int nbl = 0; nbl < 4; nbl++) {
            int n = nhalf * 32 + nbl * 8 + t * 2;
            long r0 = mB + mb * 16 + g;
            long r1 = r0 + 8;
            if (n + 1 < S_) {
                float bn0 = __ldg(&b2[n]);
                float bn1 = __ldg(&b2[n + 1]);
                float2 v0 = make_float2(acc2[nbl][0] + bn0, acc2[nbl][1] + bn1);
                float2 v1 = make_float2(acc2[nbl][2] + bn0, acc2[nbl][3] + bn1);
                *reinterpret_cast<float2*>(&g_trans[r0 * TRS + n]) = v0;
                *reinterpret_cast<float2*>(&g_trans[r1 * TRS + n]) = v1;
            } else if (n < S_) {
                float bn0 = __ldg(&b2[n]);
                g_trans[r0 * TRS + n] = acc2[nbl][0] + bn0;
                g_trans[r1 * TRS + n] = acc2[nbl][2] + bn0;
            }
        }
    }
}

// ===========================================================================
// Align (R8 version, stride TRS): one warp per 8 consecutive t of one b.
// ===========================================================================
#define TW 8
__global__ __launch_bounds__(256) void align_kernel(
    const float* __restrict__ logits, const int* __restrict__ kw,
    float* __restrict__ out)
{
    const int warp = threadIdx.x >> 5;
    const int lane = threadIdx.x & 31;
    const int task = blockIdx.x * 8 + warp;       // 0..7999
    const int b = task / (T_ / TW);
    const int t0 = (task - b * (T_ / TW)) * TW;

    const float* Lb  = logits  + (long)b * T_ * S_;
    const float* Trb = g_trans + (long)b * TM1 * TRS;

    const int s0 = lane;
    const int s1 = lane + 32;
    const bool has1 = (s1 < S_);

    float lpc0 = __ldg(&Lb[(long)t0 * S_ + s0]);
    float lpc1 = has1 ? __ldg(&Lb[(long)t0 * S_ + s1]) : 0.f;
    float trp0 = 0.f, trp1 = 0.f;
    if (t0 > 0) {
        trp0 = __ldg(&Trb[(long)(t0 - 1) * TRS + s0]);
        if (has1) trp1 = __ldg(&Trb[(long)(t0 - 1) * TRS + s1]);
    }

    #pragma unroll
    for (int i = 0; i < TW; i++) {
        const int t = t0 + i;
        float lpn0 = 0.f, lpn1 = 0.f, trc0 = 0.f, trc1 = 0.f;
        if (t < T_ - 1) {
            lpn0 = __ldg(&Lb[(long)(t + 1) * S_ + s0]);
            trc0 = __ldg(&Trb[(long)t * TRS + s0]);
            if (has1) {
                lpn1 = __ldg(&Lb[(long)(t + 1) * S_ + s1]);
                trc1 = __ldg(&Trb[(long)t * TRS + s1]);
            }
        }

        float v0, v1;
        if (t == 0) {
            float a0 = lpc0;
            float a1 = has1 ? lpc1 : -INFINITY;
            float mx = fmaxf(a0, a1);
            #pragma unroll
            for (int o = 16; o > 0; o >>= 1) mx = fmaxf(mx, __shfl_xor_sync(0xffffffff, mx, o));
            float se = __expf(a0 - mx) + (has1 ? __expf(a1 - mx) : 0.f);
            #pragma unroll
            for (int o = 16; o > 0; o >>= 1) se += __shfl_xor_sync(0xffffffff, se, o);
            float lse = mx + __logf(se);
            int k0 = __ldg(&kw[b * 32]);
            float logp0 = __ldg(&Lb[k0]) - lse;
            v0 = ((s0 == 0) ? logp0 : 0.f) + lpn0 + trc0;
            v1 = has1 ? (lpn1 + trc1) : -INFINITY;
        } else if (t == T_ - 1) {
            v0 = lpc0 + trp0;
            v1 = has1 ? (lpc1 + trp1) : -INFINITY;
        } else {
            v0 = lpc0 + lpn0 + trp0 + trc0;
            v1 = has1 ? (lpc1 + lpn1 + trp1 + trc1) : -INFINITY;
        }

        float mx = fmaxf(v0, v1);
        #pragma unroll
        for (int o = 16; o > 0; o >>= 1) mx = fmaxf(mx, __shfl_xor_sync(0xffffffff, mx, o));
        float e0 = __expf(v0 - mx);
        float e1 = has1 ? __expf(v1 - mx) : 0.f;
        float sum = e0 + e1;
        #pragma unroll
        for (int o = 16; o > 0; o >>= 1) sum += __shfl_xor_sync(0xffffffff, sum, o);
        float inv = 1.f / sum;

        float* ob = out + ((long)b * T_ + t) * S_;
        ob[s0] = e0 * inv;
        if (has1) ob[s1] = e1 * inv;

        lpc0 = lpn0; lpc1 = lpn1;
        trp0 = trc0; trp1 = trc1;
    }
}

// ===========================================================================
extern "C" void kernel_launch(void* const* d_in, const int* in_sizes, int n_in,
                              void* d_out, int out_size) {
    const float* logits = (const float*)d_in[0];   // (B,T,S)
    const float* emb    = (const float*)d_in[1];   // (B,T,H)
    const int*   kw     = (const int*)  d_in[2];   // (B,32)
    const float* W1     = (const float*)d_in[3];   // (2H,H)
    const float* b1     = (const float*)d_in[4];   // (H,)
    const float* W2     = (const float*)d_in[5];   // (H,S)
    const float* b2     = (const float*)d_in[6];   // (S,)
    float*       out    = (float*)d_out;           // (B,T,S)

    const int smem1 = 64 * 264 * 2;        // 33792
    cudaFuncSetAttribute(gemm1_fused, cudaFuncAttributeMaxDynamicSharedMemorySize, smem1);

    prep_weights<<<80, 256>>>(W1, W2);
    gemm1_fused<<<1000, 256, smem1>>>(emb, b1, b2);
    align_kernel<<<(B_ * (T_ / TW)) / 8, 256>>>(logits, kw, out);
}

// round 11
// speedup vs baseline: 1.4658x; 1.1505x over previous
#include <cuda_runtime.h>
#include <cuda_fp16.h>
#include <math.h>
#include <cstdint>

#define B_   32
#define T_   2000
#define H_   256
#define S_   63
#define TRS  64              // g_trans row stride (padded)
#define TM1  1999            // T-1
#define M1   63968           // B*(T-1)
#define M1P  64000           // padded row count
#define K1   512             // 2*H
#define N1   256             // H

// Scratch (device globals: allocation-guard safe)
__device__ __align__(16) float    g_trans[M1P * TRS];     // transition scores (stride 64)
__device__ __align__(16) uint4    g_w1pack[16384];        // W1^T fp16 A-frags
__device__ __align__(16) uint2    g_w2pack[4096];         // W2 fp16 B-frags

__device__ __forceinline__ uint32_t h2u(__half2 h) {
    return *reinterpret_cast<uint32_t*>(&h);
}

__device__ __forceinline__ void mma_f16(float* c, uint32_t a0, uint32_t a1,
                                        uint32_t a2, uint32_t a3,
                                        uint32_t b0, uint32_t b1) {
    asm volatile(
        "mma.sync.aligned.m16n8k16.row.col.f32.f16.f16.f32 "
        "{%0,%1,%2,%3}, {%4,%5,%6,%7}, {%8,%9}, {%0,%1,%2,%3};"
        : "+f"(c[0]), "+f"(c[1]), "+f"(c[2]), "+f"(c[3])
        : "r"(a0), "r"(a1), "r"(a2), "r"(a3), "r"(b0), "r"(b1));
}

__device__ __forceinline__ void ldsm4(uint32_t& r0, uint32_t& r1,
                                      uint32_t& r2, uint32_t& r3, uint32_t addr) {
    asm volatile("ldmatrix.sync.aligned.m8n8.x4.shared.b16 {%0,%1,%2,%3}, [%4];"
                 : "=r"(r0), "=r"(r1), "=r"(r2), "=r"(r3) : "r"(addr));
}

__device__ __forceinline__ uint32_t smem_u32(const void* p) {
    uint32_t a;
    asm("{ .reg .u64 t; cvta.to.shared.u64 t, %1; cvt.u32.u64 %0, t; }"
        : "=r"(a) : "l"(p));
    return a;
}

// ===========================================================================
// Prep (merged, 2x parallelism): blocks 0..127 pack W1 (uint2 per thread),
// blocks 128..143 pack W2.
// ===========================================================================
__global__ __launch_bounds__(256) void prep_weights(
    const float* __restrict__ W1, const float* __restrict__ W2)
{
    if (blockIdx.x < 128) {
        int idx  = blockIdx.x * 256 + threadIdx.x;   // 0..32767
        int sub  = idx & 1;                          // 0: k0, 1: k0+8 pair
        int fid  = idx >> 1;                         // fragment id 0..16383
        int lane  = fid & 31;
        int s     = (fid >> 5) & 1;
        int kstep = (fid >> 6) & 31;
        int q     = (fid >> 11) & 7;

        int n0 = q * 32 + s * 16 + (lane >> 2);
        int k0 = kstep * 16 + (lane & 3) * 2 + sub * 8;

        uint2 o;
        o.x = h2u(__floats2half2_rn(W1[(long)k0 * N1 + n0],     W1[(long)(k0 + 1) * N1 + n0]));
        o.y = h2u(__floats2half2_rn(W1[(long)k0 * N1 + n0 + 8], W1[(long)(k0 + 1) * N1 + n0 + 8]));
        reinterpret_cast<uint2*>(g_w1pack)[(long)fid * 2 + sub] = o;
    } else {
        int idx  = (blockIdx.x - 128) * 256 + threadIdx.x;
        if (idx >= 4096) return;
        int lane = idx & 31;
        int nb   = (idx >> 5) & 7;
        int kt   = idx >> 8;
        int k = kt * 16 + (lane & 3) * 2;
        int n = nb * 8 + (lane >> 2);
        float w00 = (n < S_) ? W2[(long)k * S_ + n]       : 0.f;
        float w01 = (n < S_) ? W2[(long)(k + 1) * S_ + n] : 0.f;
        float w10 = (n < S_) ? W2[(long)(k + 8) * S_ + n] : 0.f;
        float w11 = (n < S_) ? W2[(long)(k + 9) * S_ + n] : 0.f;
        uint2 o;
        o.x = h2u(__floats2half2_rn(w00, w01));
        o.y = h2u(__floats2half2_rn(w10, w11));
        g_w2pack[idx] = o;
    }
}

// ===========================================================================
// Fused GEMM1+GEMM2, M=32 tiles (grid 2000 -> fine wave quantization):
//   mainloop: CTA 256hid x 32m, 8 warps (hidden 32-block each), ktile=64.
//   epilogue: trans = h @ W2 + b2 from smem h tile, writes g_trans.
// ===========================================================================
#define BROW 144   // smem B row stride bytes (64 data halfs + 8 pad = 72 halfs)
__global__ __launch_bounds__(256, 2) void gemm1_fused(
    const float* __restrict__ emb, const float* __restrict__ b1,
    const float* __restrict__ b2)
{
    extern __shared__ __align__(16) char dynsm[];
    __half* sT = reinterpret_cast<__half*>(dynsm);   // [32][264] epilogue h tile
    const uint32_t sbAddr = smem_u32(dynsm);

    const int tid  = threadIdx.x;
    const int warp = tid >> 5;     // hidden 32-block (0..7)
    const int lane = tid & 31;
    const int g    = lane >> 2;
    const int t    = lane & 3;

    const int lmJ     = (lane >> 4);
    const int lmPiece = (lane >> 3) & 1;
    const int lmRow   = lane & 7;

    // B-stage mapping: 8 threads per row, 8 k-values each
    const int r  = tid >> 3;             // 0..31
    const int ch = (tid & 7) * 8;        // 0..56
    const int mBase = blockIdx.x * 32;
    int m = mBase + r;
    if (m >= M1) m = M1 - 1;
    const int b = m / TM1;
    const int tt = m - b * TM1;
    const float* rowT  = emb + ((long)b * T_ + tt) * H_;   // pairs k>=256
    const float* rowT1 = rowT + H_;                        // pairs k<256

    float acc[2][4][4];
    #pragma unroll
    for (int s = 0; s < 2; s++)
        #pragma unroll
        for (int j = 0; j < 4; j++)
            #pragma unroll
            for (int d = 0; d < 4; d++) acc[s][j][d] = 0.f;

    // prologue: stage kt=0 (kg=0 < H_)
    {
        float4 v0 = *reinterpret_cast<const float4*>(rowT1 + ch);
        float4 v1 = *reinterpret_cast<const float4*>(rowT1 + ch + 4);
        uint4 o;
        o.x = h2u(__floats2half2_rn(v0.x, v0.y));
        o.y = h2u(__floats2half2_rn(v0.z, v0.w));
        o.z = h2u(__floats2half2_rn(v1.x, v1.y));
        o.w = h2u(__floats2half2_rn(v1.z, v1.w));
        *reinterpret_cast<uint4*>(dynsm + r * BROW + (tid & 7) * 16) = o;
    }
    __syncthreads();

    for (int kt = 0; kt < 8; kt++) {
        const int cur = kt & 1;
        const uint32_t sCaddr = sbAddr + cur * (32 * BROW);

        // prefetch next 64-k chunk
        float4 vn0, vn1;
        if (kt < 7) {
            const int kg = (kt + 1) * 64;
            const float* src = (kg < H_) ? (rowT1 + kg) : (rowT + (kg - H_));
            vn0 = *reinterpret_cast<const float4*>(src + ch);
            vn1 = *reinterpret_cast<const float4*>(src + ch + 4);
        }

        #pragma unroll
        for (int ks = 0; ks < 4; ks++) {
            const int kstep = kt * 4 + ks;
            long aIdx = (((long)(warp * 32 + kstep)) * 2) * 32 + lane;
            uint4 A0 = g_w1pack[aIdx];        // s=0: n0, n0+8
            uint4 A1 = g_w1pack[aIdx + 32];   // s=1: n0+16, n0+24

            #pragma unroll
            for (int jp = 0; jp < 2; jp++) {
                int jm = jp * 2 + lmJ;
                uint32_t addr = sCaddr + (jm * 8 + lmRow) * BROW
                              + ks * 32 + lmPiece * 16;
                uint32_t r0, r1, r2, r3;
                ldsm4(r0, r1, r2, r3, addr);
                mma_f16(acc[0][jp * 2],     A0.x, A0.y, A0.z, A0.w, r0, r1);
                mma_f16(acc[1][jp * 2],     A1.x, A1.y, A1.z, A1.w, r0, r1);
                mma_f16(acc[0][jp * 2 + 1], A0.x, A0.y, A0.z, A0.w, r2, r3);
                mma_f16(acc[1][jp * 2 + 1], A1.x, A1.y, A1.z, A1.w, r2, r3);
            }
        }

        if (kt < 7) {
            uint4 o;
            o.x = h2u(__floats2half2_rn(vn0.x, vn0.y));
            o.y = h2u(__floats2half2_rn(vn0.z, vn0.w));
            o.z = h2u(__floats2half2_rn(vn1.x, vn1.y));
            o.w = h2u(__floats2half2_rn(vn1.z, vn1.w));
            *reinterpret_cast<uint4*>(dynsm + (cur ^ 1) * (32 * BROW)
                                      + r * BROW + (tid & 7) * 16) = o;
        }
        __syncthreads();
    }

    // Epilogue pass 1: +b1, relu, fp16 -> smem h tile [m 32][hid 256 (stride 264)]
    #pragma unroll
    for (int s = 0; s < 2; s++) {
        int n_g = warp * 32 + s * 16 + g;
        float bn0 = __ldg(&b1[n_g]);
        float bn8 = __ldg(&b1[n_g + 8]);
        #pragma unroll
        for (int j = 0; j < 4; j++) {
            int m_loc = j * 8 + t * 2;
            sT[m_loc * 264 + n_g]           = __float2half(fmaxf(acc[s][j][0] + bn0, 0.f));
            sT[(m_loc + 1) * 264 + n_g]     = __float2half(fmaxf(acc[s][j][1] + bn0, 0.f));
            sT[m_loc * 264 + n_g + 8]       = __float2half(fmaxf(acc[s][j][2] + bn8, 0.f));
            sT[(m_loc + 1) * 264 + n_g + 8] = __float2half(fmaxf(acc[s][j][3] + bn8, 0.f));
        }
    }
    __syncthreads();

    // Epilogue pass 2 (fused gemm2): trans = h @ W2 + b2
    //   warp w: mb = w&1 (m16-block), nq = w>>1 (16 of 64 n-cols).
    {
        const int mb = warp & 1;
        const int nq = warp >> 1;

        float acc2[2][4];
        #pragma unroll
        for (int nbl = 0; nbl < 2; nbl++)
            #pragma unroll
            for (int d = 0; d < 4; d++) acc2[nbl][d] = 0.f;

        #pragma unroll
        for (int kt = 0; kt < 16; kt++) {
            uint32_t addr = sbAddr + (mb * 16 + (lane & 15)) * 528
                          + kt * 32 + (lane >> 4) * 16;
            uint32_t a0, a1, a2, a3;
            ldsm4(a0, a1, a2, a3, addr);
            #pragma unroll
            for (int nbl = 0; nbl < 2; nbl++) {
                int nb = nq * 2 + nbl;
                uint2 bf = __ldg(&g_w2pack[((long)kt * 8 + nb) * 32 + lane]);
                mma_f16(acc2[nbl], a0, a1, a2, a3, bf.x, bf.y);
            }
        }

        const long mB = (long)blockIdx.x * 32;
        #pragma unroll
        for (int nbl = 0; nbl < 2; nbl++) {
            int n = (nq * 2 + nbl) * 8 + t * 2;
            long r0 = mB + mb * 16 + g;
            long r1 = r0 + 8;
            if (n + 1 < S_) {
                float bn0 = __ldg(&b2[n]);
                float bn1 = __ldg(&b2[n + 1]);
                float2 v0 = make_float2(acc2[nbl][0] + bn0, acc2[nbl][1] + bn1);
                float2 v1 = make_float2(acc2[nbl][2] + bn0, acc2[nbl][3] + bn1);
                *reinterpret_cast<float2*>(&g_trans[r0 * TRS + n]) = v0;
                *reinterpret_cast<float2*>(&g_trans[r1 * TRS + n]) = v1;
            } else if (n < S_) {
                float bn0 = __ldg(&b2[n]);
                g_trans[r0 * TRS + n] = acc2[nbl][0] + bn0;
                g_trans[r1 * TRS + n] = acc2[nbl][2] + bn0;
            }
        }
    }
}

// ===========================================================================
// Align (unchanged): one warp per 8 consecutive t of one b.
// ===========================================================================
#define TW 8
__global__ __launch_bounds__(256) void align_kernel(
    const float* __restrict__ logits, const int* __restrict__ kw,
    float* __restrict__ out)
{
    const int warp = threadIdx.x >> 5;
    const int lane = threadIdx.x & 31;
    const int task = blockIdx.x * 8 + warp;       // 0..7999
    const int b = task / (T_ / TW);
    const int t0 = (task - b * (T_ / TW)) * TW;

    const float* Lb  = logits  + (long)b * T_ * S_;
    const float* Trb = g_trans + (long)b * TM1 * TRS;

    const int s0 = lane;
    const int s1 = lane + 32;
    const bool has1 = (s1 < S_);

    float lpc0 = __ldg(&Lb[(long)t0 * S_ + s0]);
    float lpc1 = has1 ? __ldg(&Lb[(long)t0 * S_ + s1]) : 0.f;
    float trp0 = 0.f, trp1 = 0.f;
    if (t0 > 0) {
        trp0 = __ldg(&Trb[(long)(t0 - 1) * TRS + s0]);
        if (has1) trp1 = __ldg(&Trb[(long)(t0 - 1) * TRS + s1]);
    }

    #pragma unroll
    for (int i = 0; i < TW; i++) {
        const int t = t0 + i;
        float lpn0 = 0.f, lpn1 = 0.f, trc0 = 0.f, trc1 = 0.f;
        if (t < T_ - 1) {
            lpn0 = __ldg(&Lb[(long)(t + 1) * S_ + s0]);
            trc0 = __ldg(&Trb[(long)t * TRS + s0]);
            if (has1) {
                lpn1 = __ldg(&Lb[(long)(t + 1) * S_ + s1]);
                trc1 = __ldg(&Trb[(long)t * TRS + s1]);
            }
        }

        float v0, v1;
        if (t == 0) {
            float a0 = lpc0;
            float a1 = has1 ? lpc1 : -INFINITY;
            float mx = fmaxf(a0, a1);
            #pragma unroll
            for (int o = 16; o > 0; o >>= 1) mx = fmaxf(mx, __shfl_xor_sync(0xffffffff, mx, o));
            float se = __expf(a0 - mx) + (has1 ? __expf(a1 - mx) : 0.f);
            #pragma unroll
            for (int o = 16; o > 0; o >>= 1) se += __shfl_xor_sync(0xffffffff, se, o);
            float lse = mx + __logf(se);
            int k0 = __ldg(&kw[b * 32]);
            float logp0 = __ldg(&Lb[k0]) - lse;
            v0 = ((s0 == 0) ? logp0 : 0.f) + lpn0 + trc0;
            v1 = has1 ? (lpn1 + trc1) : -INFINITY;
        } else if (t == T_ - 1) {
            v0 = lpc0 + trp0;
            v1 = has1 ? (lpc1 + trp1) : -INFINITY;
        } else {
            v0 = lpc0 + lpn0 + trp0 + trc0;
            v1 = has1 ? (lpc1 + lpn1 + trp1 + trc1) : -INFINITY;
        }

        float mx = fmaxf(v0, v1);
        #pragma unroll
        for (int o = 16; o > 0; o >>= 1) mx = fmaxf(mx, __shfl_xor_sync(0xffffffff, mx, o));
        float e0 = __expf(v0 - mx);
        float e1 = has1 ? __expf(v1 - mx) : 0.f;
        float sum = e0 + e1;
        #pragma unroll
        for (int o = 16; o > 0; o >>= 1) sum += __shfl_xor_sync(0xffffffff, sum, o);
        float inv = 1.f / sum;

        float* ob = out + ((long)b * T_ + t) * S_;
        ob[s0] = e0 * inv;
        if (has1) ob[s1] = e1 * inv;

        lpc0 = lpn0; lpc1 = lpn1;
        trp0 = trc0; trp1 = trc1;
    }
}

// ===========================================================================
extern "C" void kernel_launch(void* const* d_in, const int* in_sizes, int n_in,
                              void* d_out, int out_size) {
    const float* logits = (const float*)d_in[0];   // (B,T,S)
    const float* emb    = (const float*)d_in[1];   // (B,T,H)
    const int*   kw     = (const int*)  d_in[2];   // (B,32)
    const float* W1     = (const float*)d_in[3];   // (2H,H)
    const float* b1     = (const float*)d_in[4];   // (H,)
    const float* W2     = (const float*)d_in[5];   // (H,S)
    const float* b2     = (const float*)d_in[6];   // (S,)
    float*       out    = (float*)d_out;           // (B,T,S)

    const int smem1 = 32 * 264 * 2;        // 16896 (>= 2*32*144 = 9216)
    cudaFuncSetAttribute(gemm1_fused, cudaFuncAttributeMaxDynamicSharedMemorySize, smem1);

    prep_weights<<<144, 256>>>(W1, W2);
    gemm1_fused<<<2000, 256, smem1>>>(emb, b1, b2);
    align_kernel<<<(B_ * (T_ / TW)) / 8, 256>>>(logits, kw, out);
}